// round 7
// baseline (speedup 1.0000x reference)
#include <cuda_runtime.h>

// PhiCell: Phi is identity => outputs = inputs * k; new_state = outputs[T-1].
// Exact-cover streaming scale with a FORCED load/store phase split:
// an asm memory barrier between the 8 LDG.128 and the 8 STG.128 prevents
// ptxas from pairwise-interleaving them (which it did every prior round,
// collapsing MLP to ~2 and pinning read BW at ~2.1 TB/s).

#define VPT 8
#define THREADS 256

__global__ void __launch_bounds__(THREADS, 1) phicell_forced(
    const float4* __restrict__ in4,
    const float*  __restrict__ kptr,
    float4*       __restrict__ out4,
    int n, int out_size)
{
    const int base = blockIdx.x * (THREADS * VPT) + threadIdx.x;
    const float4* ip = in4 + base;
    float4*       op = out4 + base;

    // ---- load phase: 8 independent LDG.128 ----
    float4 v0 = ip[0 * THREADS];
    float4 v1 = ip[1 * THREADS];
    float4 v2 = ip[2 * THREADS];
    float4 v3 = ip[3 * THREADS];
    float4 v4 = ip[4 * THREADS];
    float4 v5 = ip[5 * THREADS];
    float4 v6 = ip[6 * THREADS];
    float4 v7 = ip[7 * THREADS];
    const float k = __ldg(kptr);

    // Scheduling fence: loads cannot sink below, stores cannot hoist above.
    // Forces all 8 vectors live simultaneously -> true MLP_p1 = 8 in SASS.
    asm volatile("" ::: "memory");

    // ---- compute + store phase ----
    v0.x *= k; v0.y *= k; v0.z *= k; v0.w *= k;
    v1.x *= k; v1.y *= k; v1.z *= k; v1.w *= k;
    v2.x *= k; v2.y *= k; v2.z *= k; v2.w *= k;
    v3.x *= k; v3.y *= k; v3.z *= k; v3.w *= k;
    v4.x *= k; v4.y *= k; v4.z *= k; v4.w *= k;
    v5.x *= k; v5.y *= k; v5.z *= k; v5.w *= k;
    v6.x *= k; v6.y *= k; v6.z *= k; v6.w *= k;
    v7.x *= k; v7.y *= k; v7.z *= k; v7.w *= k;

    op[0 * THREADS] = v0;
    op[1 * THREADS] = v1;
    op[2 * THREADS] = v2;
    op[3 * THREADS] = v3;
    op[4 * THREADS] = v4;
    op[5 * THREADS] = v5;
    op[6 * THREADS] = v6;
    op[7 * THREADS] = v7;

    // Owner of the final element writes the state slot(s).
    if (base + 7 * THREADS == (n >> 2) - 1) {
        float* outs = (float*)out4;
        for (int s = n; s < out_size; ++s) outs[s] = v7.w;
    }
}

// Generic fallback for non-multiple shapes.
__global__ void __launch_bounds__(256) phicell_generic(
    const float* __restrict__ in,
    const float* __restrict__ kptr,
    float*       __restrict__ out,
    int n, int out_size)
{
    const float k = __ldg(kptr);
    const int i = blockIdx.x * blockDim.x + threadIdx.x;
    const int base = i << 2;
    if (base + 3 < n) {
        float4 v = *reinterpret_cast<const float4*>(in + base);
        v.x *= k; v.y *= k; v.z *= k; v.w *= k;
        *reinterpret_cast<float4*>(out + base) = v;
        if (base + 4 == n)
            for (int j = n; j < out_size; ++j) out[j] = v.w;
    } else if (base < n) {
        float last = 0.f;
        for (int idx = base; idx < n; ++idx) { last = in[idx] * k; out[idx] = last; }
        for (int j = n; j < out_size; ++j) out[j] = last;
    }
}

extern "C" void kernel_launch(void* const* d_in, const int* in_sizes, int n_in,
                              void* d_out, int out_size)
{
    const float* in  = (const float*)d_in[0];   // inputs [1, T]
    // d_in[1] = state [1,1] (unused: Phi identity -> output state-independent)
    const float* kpt = (const float*)d_in[2];   // kernel [1,1]
    float* out = (float*)d_out;

    const int n  = in_sizes[0];
    const int per_block = THREADS * VPT * 4;    // 8192 elements per block

    if ((n % per_block) == 0) {
        const int blk = n / per_block;          // 512 for T=4194304
        phicell_forced<<<blk, THREADS>>>(
            (const float4*)in, kpt, (float4*)out, n, out_size);
    } else {
        const int nt  = (n + 3) >> 2;
        const int blk = (nt + 255) / 256;
        phicell_generic<<<blk > 0 ? blk : 1, 256>>>(in, kpt, out, n, out_size);
    }
}

// round 8
// speedup vs baseline: 1.0036x; 1.0036x over previous
#include <cuda_runtime.h>

// PhiCell: Phi is identity => outputs = inputs * k; new_state = outputs[T-1].
// R8: 256-bit global accesses (sm_103a / PTX 8.7). 4 x LDG.256 per thread,
// phase-fenced, exact cover: 512 blocks x 256 threads x 4 float8.
// Halves instruction count and L1tex wavefront entries per byte vs LDG.128.

#define V8PT 4     // float8 (32B) vectors per thread
#define THREADS 256

struct __align__(32) f8 { float a,b,c,d,e,f,g,h; };

__device__ __forceinline__ f8 ldg256(const f8* p) {
    f8 v;
    asm volatile("ld.global.v8.f32 {%0,%1,%2,%3,%4,%5,%6,%7}, [%8];"
                 : "=f"(v.a), "=f"(v.b), "=f"(v.c), "=f"(v.d),
                   "=f"(v.e), "=f"(v.f), "=f"(v.g), "=f"(v.h)
                 : "l"(p));
    return v;
}
__device__ __forceinline__ void stg256(f8* p, const f8& v) {
    asm volatile("st.global.v8.f32 [%8], {%0,%1,%2,%3,%4,%5,%6,%7};"
                 :: "f"(v.a), "f"(v.b), "f"(v.c), "f"(v.d),
                    "f"(v.e), "f"(v.f), "f"(v.g), "f"(v.h),
                    "l"(p) : "memory");
}

__global__ void __launch_bounds__(THREADS, 1) phicell_v256(
    const f8* __restrict__ in8,
    const float* __restrict__ kptr,
    f8* __restrict__ out8,
    int n, int out_size)
{
    const int base = blockIdx.x * (THREADS * V8PT) + threadIdx.x;
    const f8* ip = in8 + base;
    f8*       op = out8 + base;

    // ---- load phase: 4 independent LDG.256 ----
    f8 v0 = ldg256(ip + 0 * THREADS);
    f8 v1 = ldg256(ip + 1 * THREADS);
    f8 v2 = ldg256(ip + 2 * THREADS);
    f8 v3 = ldg256(ip + 3 * THREADS);
    const float k = __ldg(kptr);

    asm volatile("" ::: "memory");  // keep loads front-batched

    // ---- compute + store phase ----
#define SCALE(v) v.a*=k; v.b*=k; v.c*=k; v.d*=k; v.e*=k; v.f*=k; v.g*=k; v.h*=k;
    SCALE(v0) SCALE(v1) SCALE(v2) SCALE(v3)
#undef SCALE

    stg256(op + 0 * THREADS, v0);
    stg256(op + 1 * THREADS, v1);
    stg256(op + 2 * THREADS, v2);
    stg256(op + 3 * THREADS, v3);

    // Owner of the final float8 writes the state slot(s).
    if (base + 3 * THREADS == (n >> 3) - 1) {
        float* outs = (float*)out8;
        for (int s = n; s < out_size; ++s) outs[s] = v3.h;
    }
}

// Generic fallback for non-multiple shapes.
__global__ void __launch_bounds__(256) phicell_generic(
    const float* __restrict__ in,
    const float* __restrict__ kptr,
    float*       __restrict__ out,
    int n, int out_size)
{
    const float k = __ldg(kptr);
    const int i = blockIdx.x * blockDim.x + threadIdx.x;
    const int base = i << 2;
    if (base + 3 < n) {
        float4 v = *reinterpret_cast<const float4*>(in + base);
        v.x *= k; v.y *= k; v.z *= k; v.w *= k;
        *reinterpret_cast<float4*>(out + base) = v;
        if (base + 4 == n)
            for (int j = n; j < out_size; ++j) out[j] = v.w;
    } else if (base < n) {
        float last = 0.f;
        for (int idx = base; idx < n; ++idx) { last = in[idx] * k; out[idx] = last; }
        for (int j = n; j < out_size; ++j) out[j] = last;
    }
}

extern "C" void kernel_launch(void* const* d_in, const int* in_sizes, int n_in,
                              void* d_out, int out_size)
{
    const float* in  = (const float*)d_in[0];   // inputs [1, T]
    // d_in[1] = state [1,1] (unused: Phi identity -> output state-independent)
    const float* kpt = (const float*)d_in[2];   // kernel [1,1]
    float* out = (float*)d_out;

    const int n  = in_sizes[0];
    const int per_block = THREADS * V8PT * 8;   // 8192 elements per block

    if ((n % per_block) == 0) {
        const int blk = n / per_block;          // 512 for T=4194304
        phicell_v256<<<blk, THREADS>>>(
            (const f8*)in, kpt, (f8*)out, n, out_size);
    } else {
        const int nt  = (n + 3) >> 2;
        const int blk = (nt + 255) / 256;
        phicell_generic<<<blk > 0 ? blk : 1, 256>>>(in, kpt, out, n, out_size);
    }
}